// round 13
// baseline (speedup 1.0000x reference)
#include <cuda_runtime.h>
#include <math.h>

// ---------------------------------------------------------------------------
// NoisyTopkRouter: B=128, T1=128, T2=8, D=1024, E=64
// Two kernels, GEMV distributed into the pool:
//  1) pool_gemv_kernel: grid (NSLICE=8, B) x 256 thr. Block (ds,b) sums ALL
//     1024 t-rows of D-slice [ds*128,(ds+1)*128) (HBM stream; warp = one row
//     = 512B coalesced, unroll-8), reduces across warps in smem, scales by
//     1/1024, then computes PARTIAL LOGITS for all 64 experts x 2 matrices
//     against W[:,slice] (64KB, L2-shared by the 128 blocks with same ds).
//     GEMV runs on idle fma/shfl pipes, hidden under the DRAM stream.
//     Output: g_plog[b][ds][e] (route) / [b][8+ds'][e]-style noise half.
//  2) router_kernel: 128 blocks x 64 thr. Sums 8 slice-partials per (b,e)
//     from the 512KB L2-hot plog buffer, adds bias, runs the proven softmax/
//     rank/pad-quirk chain. Tiny (~1-2us) vs old 6us 4MB+512KB router.
// Outputs: router_output [B,E] then noisy [B,E].
// ---------------------------------------------------------------------------

#define B_ 128
#define TT 1024   // T1*T2
#define D_ 1024
#define E_ 64
#define NSLICE 8
#define DS 128    // floats per D-slice

// partial logits: [b][ route: ds*64+e | noise: 512 + ds*64+e ] = 512 KB
__device__ float g_plog[B_ * 2 * NSLICE * E_];

__global__ void __launch_bounds__(256) pool_gemv_kernel(
    const float* __restrict__ mh,
    const float* __restrict__ W_route,
    const float* __restrict__ W_noise)
{
    __shared__ __align__(16) float4 sbuf[8][32];
    __shared__ __align__(16) float4 pooled4[32];

    const int ds   = blockIdx.x;
    const int b    = blockIdx.y;
    const int tid  = threadIdx.x;
    const int lane = tid & 31;
    const int w    = tid >> 5;    // warp = row-within-group-of-8

    // --- phase 1: stream-sum rows t ≡ w (mod 8) over this D-slice ---
    {
        const float4* base = reinterpret_cast<const float4*>(
            mh + (size_t)b * TT * D_ + (size_t)ds * DS) + lane;
        float4 acc = make_float4(0.f, 0.f, 0.f, 0.f);
#pragma unroll 8
        for (int i = 0; i < TT / 8; ++i) {
            float4 v = __ldcs(base + (size_t)(i * 8 + w) * (D_ / 4));
            acc.x += v.x; acc.y += v.y; acc.z += v.z; acc.w += v.w;
        }
        sbuf[w][lane] = acc;
    }
    __syncthreads();

    // --- cross-warp reduce + mean scale: warp 0 builds pooled slice ---
    if (tid < 32) {
        float4 s = sbuf[0][tid];
#pragma unroll
        for (int rr = 1; rr < 8; ++rr) {
            float4 v = sbuf[rr][tid];
            s.x += v.x; s.y += v.y; s.z += v.z; s.w += v.w;
        }
        const float inv = 1.0f / (float)TT;
        s.x *= inv; s.y *= inv; s.z *= inv; s.w *= inv;
        pooled4[tid] = s;
    }
    __syncthreads();

    // --- phase 2: partial GEMV for this slice; warp w -> experts [8w, 8w+8) ---
    {
        const float4 p4 = pooled4[lane];
        float* plog = g_plog + (size_t)b * (2 * NSLICE * E_) + ds * E_;
#pragma unroll
        for (int ei = 0; ei < 8; ++ei) {
            const int e = w * 8 + ei;
            float4 a = __ldg(reinterpret_cast<const float4*>(
                W_route + (size_t)e * D_ + (size_t)ds * DS) + lane);
            float4 c = __ldg(reinterpret_cast<const float4*>(
                W_noise + (size_t)e * D_ + (size_t)ds * DS) + lane);
            float dr = p4.x * a.x + p4.y * a.y + p4.z * a.z + p4.w * a.w;
            float dn = p4.x * c.x + p4.y * c.y + p4.z * c.z + p4.w * c.w;
#pragma unroll
            for (int o = 16; o; o >>= 1) {
                dr += __shfl_xor_sync(0xffffffffu, dr, o);
                dn += __shfl_xor_sync(0xffffffffu, dn, o);
            }
            if (lane == 0) {
                plog[e] = dr;                     // route partial
                plog[NSLICE * E_ + e] = dn;       // noise partial
            }
        }
    }
}

__device__ __forceinline__ float softplus_f(float x) {
    // jax.nn.softplus = logaddexp(x, 0)
    return fmaxf(x, 0.f) + log1pf(expf(-fabsf(x)));
}

// 128 blocks x 64 threads; thread = expert e of batch b.
__global__ void __launch_bounds__(64) router_kernel(
    const float* __restrict__ b_route, const float* __restrict__ b_noise,
    const float* __restrict__ noise_eps, const int* __restrict__ mis_mask,
    float* __restrict__ out, int out_size)
{
    __shared__ float lraw[E_], nraw[E_];
    __shared__ float ebuf1[E_], ebuf2[E_];
    __shared__ float noisy_s[E_], sparse_s[E_];

    const int b   = blockIdx.x;
    const int tid = threadIdx.x;   // = expert e

    // --- gather partial logits (512KB buffer, L2-hot) + bias ---
    {
        const float* plog = g_plog + (size_t)b * (2 * NSLICE * E_);
        float lr = b_route[tid], nr = b_noise[tid];
#pragma unroll
        for (int dsv = 0; dsv < NSLICE; ++dsv) {
            lr += plog[dsv * E_ + tid];
            nr += plog[NSLICE * E_ + dsv * E_ + tid];
        }
        lraw[tid] = lr;
        nraw[tid] = nr;
    }
    __syncthreads();

    // --- proven scalar chain (tid < 64 == all threads here) ---
    float logit = 0.f;

    {
        float m1 = -INFINITY;
#pragma unroll
        for (int j = 0; j < E_; ++j) m1 = fmaxf(m1, lraw[j]);
        ebuf1[tid] = expf(lraw[tid] - m1);
        nraw[tid] = noise_eps[b * E_ + tid] * softplus_f(nraw[tid]);
    }
    __syncthreads();

    {
        float s1 = 0.f;
#pragma unroll
        for (int j = 0; j < E_; ++j) s1 += ebuf1[j];
        logit = ebuf1[tid] / s1;

        float m2 = -INFINITY;
#pragma unroll
        for (int j = 0; j < E_; ++j) m2 = fmaxf(m2, nraw[j]);
        ebuf2[tid] = expf(nraw[tid] - m2);
    }
    __syncthreads();

    {
        float s2 = 0.f;
#pragma unroll
        for (int j = 0; j < E_; ++j) s2 += ebuf2[j];
        float noisy = logit + ebuf2[tid] / s2;
        noisy_s[tid] = noisy;
        if (out_size >= 2 * B_ * E_)
            out[B_ * E_ + b * E_ + tid] = noisy;   // second output: noisy
    }
    __syncthreads();

    {
        // stable descending rank (ties -> lower index first)
        const float myv = noisy_s[tid];
        int rank = 0;
#pragma unroll
        for (int j = 0; j < E_; ++j) {
            float vj = noisy_s[j];
            rank += (vj > myv) || (vj == myv && j < tid);
        }
        const int k = mis_mask[b];
        float sp = (rank < k) ? myv : 0.f;
        if (k < E_ && tid == 0) sp = 0.f;   // torch pad-scatter quirk
        sparse_s[tid] = sp;
    }
    __syncthreads();

    {
        float m3 = -INFINITY;
#pragma unroll
        for (int j = 0; j < E_; ++j) m3 = fmaxf(m3, sparse_s[j]);
        ebuf1[tid] = expf(sparse_s[tid] - m3);
    }
    __syncthreads();

    {
        float s3 = 0.f;
#pragma unroll
        for (int j = 0; j < E_; ++j) s3 += ebuf1[j];
        out[b * E_ + tid] = ebuf1[tid] / s3;       // first output: router_output
    }
}

extern "C" void kernel_launch(void* const* d_in, const int* in_sizes, int n_in,
                              void* d_out, int out_size) {
    const float* mh        = (const float*)d_in[0];
    const float* W_route   = (const float*)d_in[1];
    const float* b_route   = (const float*)d_in[2];
    const float* W_noise   = (const float*)d_in[3];
    const float* b_noise   = (const float*)d_in[4];
    const float* noise_eps = (const float*)d_in[5];
    const int*   mis_mask  = (const int*)d_in[6];
    float* out = (float*)d_out;

    dim3 g1(NSLICE, B_);
    pool_gemv_kernel<<<g1, 256>>>(mh, W_route, W_noise);
    router_kernel<<<B_, 64>>>(b_route, b_noise, noise_eps, mis_mask,
                              out, out_size);
}

// round 14
// speedup vs baseline: 1.1049x; 1.1049x over previous
#include <cuda_runtime.h>
#include <math.h>

// ---------------------------------------------------------------------------
// NoisyTopkRouter: B=128, T1=128, T2=8, D=1024, E=64
// R10 kernels (proven 88.1us, rel_err 2.9e-7) + graph-level fork/join:
//   poolA (b 0..95)  -> [fork] routerA (b 0..95, stream s2)  || poolB (b 96..127)
//   [join] -> routerB (b 96..127)
// routerA (~6us) hides under poolB's ~13us stream; only routerB is exposed.
// Kernels are bit-identical math to R10 (b_base offsets only).
// Outputs: router_output [B,E] then noisy [B,E].
// ---------------------------------------------------------------------------

#define B_ 128
#define TT 1024   // T1*T2
#define D_ 1024
#define E_ 64
#define TSPLIT 8
#define TCHUNK (TT / TSPLIT)  // 128
#define B_A 96                // batches in first pool/router pair
#define B_B (B_ - B_A)        // 32

// partials: [B][TSPLIT][256] float4 = 4 MiB
__device__ float4 g_partial[B_ * TSPLIT * 256];

__global__ void __launch_bounds__(256) pool_kernel(const float* __restrict__ mh,
                                                   int b_base) {
    const int b   = b_base + blockIdx.x;
    const int ts  = blockIdx.y;
    const int tid = threadIdx.x;

    const float4* p = reinterpret_cast<const float4*>(
        mh + ((size_t)b * TT + (size_t)ts * TCHUNK) * D_) + tid;

    float4 acc = make_float4(0.f, 0.f, 0.f, 0.f);
#pragma unroll 8
    for (int t = 0; t < TCHUNK; ++t) {
        float4 v = __ldcs(p + (size_t)t * (D_ / 4));  // streaming: no reuse
        acc.x += v.x; acc.y += v.y; acc.z += v.z; acc.w += v.w;
    }
    g_partial[(b * TSPLIT + ts) * 256 + tid] = acc;
}

__device__ __forceinline__ float softplus_f(float x) {
    // jax.nn.softplus = logaddexp(x, 0)
    return fmaxf(x, 0.f) + log1pf(expf(-fabsf(x)));
}

// blocks x 1024 threads; one batch per block (b = b_base + blockIdx.x).
// Warp w: experts w and w+32, both matrices.
__global__ void __launch_bounds__(1024) router_kernel(
    const float* __restrict__ W_route, const float* __restrict__ b_route,
    const float* __restrict__ W_noise, const float* __restrict__ b_noise,
    const float* __restrict__ noise_eps, const int* __restrict__ mis_mask,
    float* __restrict__ out, int out_size, int b_base)
{
    __shared__ __align__(16) float pooled[D_];
    __shared__ float lraw[E_], nraw[E_];
    __shared__ float ebuf1[E_], ebuf2[E_];
    __shared__ float noisy_s[E_], sparse_s[E_];

    const int b   = b_base + blockIdx.x;
    const int tid = threadIdx.x;

    // --- W L2-warm preamble: global slice b covers a distinct 4KB
    //     (2KB per matrix); 128 slices over the two launches = all 512KB. ---
    {
        const char* wr = reinterpret_cast<const char*>(W_route) + (size_t)b * 2048;
        const char* wn = reinterpret_cast<const char*>(W_noise) + (size_t)b * 2048;
        if (tid < 16)
            asm volatile("prefetch.global.L2 [%0];" :: "l"(wr + (size_t)tid * 128));
        else if (tid < 32)
            asm volatile("prefetch.global.L2 [%0];" :: "l"(wn + (size_t)(tid - 16) * 128));
    }

    // --- finish pooling: thread owns d=tid, sums 8 partials ---
    {
        const float* gp = reinterpret_cast<const float*>(g_partial);
        float acc = 0.f;
#pragma unroll
        for (int t = 0; t < TSPLIT; ++t)
            acc += gp[((size_t)(b * TSPLIT + t)) * 1024 + tid];
        pooled[tid] = acc * (1.0f / (float)TT);
    }
    __syncthreads();

    // --- dual GEMV: warp w -> experts w and w+32; float4 lanes over D ---
    {
        const int w = tid >> 5, lane = tid & 31;
        const float4* pooled4 = reinterpret_cast<const float4*>(pooled);
#pragma unroll
        for (int ei = 0; ei < 2; ++ei) {
            const int e = w + ei * 32;
            const float4* wr = reinterpret_cast<const float4*>(W_route) + (size_t)e * (D_ / 4);
            const float4* wn = reinterpret_cast<const float4*>(W_noise) + (size_t)e * (D_ / 4);
            float ar = 0.f, an = 0.f;
#pragma unroll
            for (int j = lane; j < D_ / 4; j += 32) {
                float4 pv = pooled4[j];
                float4 a  = __ldg(wr + j);
                float4 c  = __ldg(wn + j);
                ar += pv.x * a.x + pv.y * a.y + pv.z * a.z + pv.w * a.w;
                an += pv.x * c.x + pv.y * c.y + pv.z * c.z + pv.w * c.w;
            }
#pragma unroll
            for (int o = 16; o; o >>= 1) {
                ar += __shfl_xor_sync(0xffffffffu, ar, o);
                an += __shfl_xor_sync(0xffffffffu, an, o);
            }
            if (lane == 0) {
                lraw[e] = ar + b_route[e];
                nraw[e] = an + b_noise[e];
            }
        }
    }
    __syncthreads();

    // --- per-expert scalar chain; tid<64 active, all threads hit syncthreads ---
    float logit = 0.f;

    if (tid < E_) {
        float m1 = -INFINITY;
#pragma unroll
        for (int j = 0; j < E_; ++j) m1 = fmaxf(m1, lraw[j]);
        ebuf1[tid] = expf(lraw[tid] - m1);
        nraw[tid] = noise_eps[b * E_ + tid] * softplus_f(nraw[tid]);
    }
    __syncthreads();

    if (tid < E_) {
        float s1 = 0.f;
#pragma unroll
        for (int j = 0; j < E_; ++j) s1 += ebuf1[j];
        logit = ebuf1[tid] / s1;

        float m2 = -INFINITY;
#pragma unroll
        for (int j = 0; j < E_; ++j) m2 = fmaxf(m2, nraw[j]);
        ebuf2[tid] = expf(nraw[tid] - m2);
    }
    __syncthreads();

    if (tid < E_) {
        float s2 = 0.f;
#pragma unroll
        for (int j = 0; j < E_; ++j) s2 += ebuf2[j];
        float noisy = logit + ebuf2[tid] / s2;
        noisy_s[tid] = noisy;
        if (out_size >= 2 * B_ * E_)
            out[B_ * E_ + b * E_ + tid] = noisy;   // second output: noisy
    }
    __syncthreads();

    if (tid < E_) {
        // stable descending rank (ties -> lower index first)
        const float myv = noisy_s[tid];
        int rank = 0;
#pragma unroll
        for (int j = 0; j < E_; ++j) {
            float vj = noisy_s[j];
            rank += (vj > myv) || (vj == myv && j < tid);
        }
        const int k = mis_mask[b];
        float sp = (rank < k) ? myv : 0.f;
        if (k < E_ && tid == 0) sp = 0.f;   // torch pad-scatter quirk
        sparse_s[tid] = sp;
    }
    __syncthreads();

    if (tid < E_) {
        float m3 = -INFINITY;
#pragma unroll
        for (int j = 0; j < E_; ++j) m3 = fmaxf(m3, sparse_s[j]);
        ebuf1[tid] = expf(sparse_s[tid] - m3);
    }
    __syncthreads();

    if (tid < E_) {
        float s3 = 0.f;
#pragma unroll
        for (int j = 0; j < E_; ++j) s3 += ebuf1[j];
        out[b * E_ + tid] = ebuf1[tid] / s3;       // first output: router_output
    }
}

extern "C" void kernel_launch(void* const* d_in, const int* in_sizes, int n_in,
                              void* d_out, int out_size) {
    const float* mh        = (const float*)d_in[0];
    const float* W_route   = (const float*)d_in[1];
    const float* b_route   = (const float*)d_in[2];
    const float* W_noise   = (const float*)d_in[3];
    const float* b_noise   = (const float*)d_in[4];
    const float* noise_eps = (const float*)d_in[5];
    const int*   mis_mask  = (const int*)d_in[6];
    float* out = (float*)d_out;

    // one-time host-side resources (created on the correctness call, i.e.
    // before graph capture; host objects only — no device allocation)
    static cudaStream_t s2 = nullptr;
    static cudaEvent_t  evFork = nullptr, evJoin = nullptr;
    if (s2 == nullptr) {
        cudaStreamCreateWithFlags(&s2, cudaStreamNonBlocking);
        cudaEventCreateWithFlags(&evFork, cudaEventDisableTiming);
        cudaEventCreateWithFlags(&evJoin, cudaEventDisableTiming);
    }

    // poolA: batches 0..95
    pool_kernel<<<dim3(B_A, TSPLIT), 256>>>(mh, 0);

    // fork: routerA (batches 0..95) on s2, concurrent with poolB
    cudaEventRecord(evFork, 0);
    cudaStreamWaitEvent(s2, evFork, 0);
    router_kernel<<<B_A, 1024, 0, s2>>>(W_route, b_route, W_noise, b_noise,
                                        noise_eps, mis_mask, out, out_size, 0);
    cudaEventRecord(evJoin, s2);

    // poolB: batches 96..127 (runs concurrently with routerA)
    pool_kernel<<<dim3(B_B, TSPLIT), 256>>>(mh, B_A);

    // join, then routerB: batches 96..127
    cudaStreamWaitEvent(0, evJoin, 0);
    router_kernel<<<B_B, 1024>>>(W_route, b_route, W_noise, b_noise,
                                 noise_eps, mis_mask, out, out_size, B_A);
}

// round 15
// speedup vs baseline: 1.2171x; 1.1016x over previous
#include <cuda_runtime.h>
#include <math.h>

// ---------------------------------------------------------------------------
// NoisyTopkRouter: B=128, T1=128, T2=8, D=1024, E=64
// SINGLE kernel, one CTA per batch: 128 CTAs x 1024 threads.
//  - Stream phase: CTA reads its contiguous 4MB batch; thread tid owns
//    row-class r0=tid>>8 and float4-column c=tid&255; 4 rows/step, 256 steps,
//    unroll-8. Warp accesses = 512B contiguous. No partials, no 2nd kernel.
//  - Reduce: 16KB smem (1024 float4), 4 row-classes summed -> pooled[1024].
//  - Router: proven GEMV (warp w -> experts w, w+32; float4 over D) +
//    softmax/softplus/rank/pad-quirk chain (rel_err 2.9e-7 pedigree).
// Zero cross-block communication -> fully deterministic.
// Outputs: router_output [B,E] then noisy [B,E].
// ---------------------------------------------------------------------------

#define B_ 128
#define TT 1024   // T1*T2
#define D_ 1024
#define E_ 64

__device__ __forceinline__ float softplus_f(float x) {
    // jax.nn.softplus = logaddexp(x, 0)
    return fmaxf(x, 0.f) + log1pf(expf(-fabsf(x)));
}

__global__ void __launch_bounds__(1024) fused_batch_kernel(
    const float* __restrict__ mh,
    const float* __restrict__ W_route, const float* __restrict__ b_route,
    const float* __restrict__ W_noise, const float* __restrict__ b_noise,
    const float* __restrict__ noise_eps, const int* __restrict__ mis_mask,
    float* __restrict__ out, int out_size)
{
    __shared__ __align__(16) float4 sbuf[1024];     // 16 KB reduce buffer
    __shared__ __align__(16) float pooled[D_];      // 4 KB pooled vector
    __shared__ float lraw[E_], nraw[E_];
    __shared__ float ebuf1[E_], ebuf2[E_];
    __shared__ float noisy_s[E_], sparse_s[E_];

    const int b   = blockIdx.x;
    const int tid = threadIdx.x;

    // ---------------- phase 1: stream the whole batch (4 MB) ----------------
    {
        const int r0 = tid >> 8;        // row-class 0..3
        const int c  = tid & 255;       // float4 column
        const float4* base = reinterpret_cast<const float4*>(mh)
                           + ((size_t)b * TT + r0) * (D_ / 4) + c;
        float4 acc = make_float4(0.f, 0.f, 0.f, 0.f);
#pragma unroll 8
        for (int i = 0; i < TT / 4; ++i) {
            float4 v = __ldcs(base + (size_t)i * D_);  // +4 rows per step
            acc.x += v.x; acc.y += v.y; acc.z += v.z; acc.w += v.w;
        }
        sbuf[tid] = acc;
    }

    // warm this CTA's 4KB W slice into L2 (128 CTAs cover all 512KB)
    {
        const char* wr = reinterpret_cast<const char*>(W_route) + (size_t)b * 2048;
        const char* wn = reinterpret_cast<const char*>(W_noise) + (size_t)b * 2048;
        if (tid < 16)
            asm volatile("prefetch.global.L2 [%0];" :: "l"(wr + (size_t)tid * 128));
        else if (tid < 32)
            asm volatile("prefetch.global.L2 [%0];" :: "l"(wn + (size_t)(tid - 16) * 128));
    }
    __syncthreads();

    // ---------------- reduce 4 row-classes -> pooled ----------------
    if (tid < 256) {
        float4 s = sbuf[tid];
        float4 v1 = sbuf[256 + tid];
        float4 v2 = sbuf[512 + tid];
        float4 v3 = sbuf[768 + tid];
        s.x += v1.x + v2.x + v3.x;
        s.y += v1.y + v2.y + v3.y;
        s.z += v1.z + v2.z + v3.z;
        s.w += v1.w + v2.w + v3.w;
        const float inv = 1.0f / (float)TT;
        reinterpret_cast<float4*>(pooled)[tid] =
            make_float4(s.x * inv, s.y * inv, s.z * inv, s.w * inv);
    }
    __syncthreads();

    // ---------------- dual GEMV: warp w -> experts w and w+32 ----------------
    {
        const int w = tid >> 5, lane = tid & 31;
        const float4* pooled4 = reinterpret_cast<const float4*>(pooled);
#pragma unroll
        for (int ei = 0; ei < 2; ++ei) {
            const int e = w + ei * 32;
            const float4* wr = reinterpret_cast<const float4*>(W_route) + (size_t)e * (D_ / 4);
            const float4* wn = reinterpret_cast<const float4*>(W_noise) + (size_t)e * (D_ / 4);
            float ar = 0.f, an = 0.f;
#pragma unroll
            for (int j = lane; j < D_ / 4; j += 32) {
                float4 pv = pooled4[j];
                float4 a  = __ldg(wr + j);
                float4 c  = __ldg(wn + j);
                ar += pv.x * a.x + pv.y * a.y + pv.z * a.z + pv.w * a.w;
                an += pv.x * c.x + pv.y * c.y + pv.z * c.z + pv.w * c.w;
            }
#pragma unroll
            for (int o = 16; o; o >>= 1) {
                ar += __shfl_xor_sync(0xffffffffu, ar, o);
                an += __shfl_xor_sync(0xffffffffu, an, o);
            }
            if (lane == 0) {
                lraw[e] = ar + b_route[e];
                nraw[e] = an + b_noise[e];
            }
        }
    }
    __syncthreads();

    // ---------------- per-expert scalar chain (tid<64 active) ----------------
    float logit = 0.f;

    if (tid < E_) {
        float m1 = -INFINITY;
#pragma unroll
        for (int j = 0; j < E_; ++j) m1 = fmaxf(m1, lraw[j]);
        ebuf1[tid] = expf(lraw[tid] - m1);
        nraw[tid] = noise_eps[b * E_ + tid] * softplus_f(nraw[tid]);
    }
    __syncthreads();

    if (tid < E_) {
        float s1 = 0.f;
#pragma unroll
        for (int j = 0; j < E_; ++j) s1 += ebuf1[j];
        logit = ebuf1[tid] / s1;

        float m2 = -INFINITY;
#pragma unroll
        for (int j = 0; j < E_; ++j) m2 = fmaxf(m2, nraw[j]);
        ebuf2[tid] = expf(nraw[tid] - m2);
    }
    __syncthreads();

    if (tid < E_) {
        float s2 = 0.f;
#pragma unroll
        for (int j = 0; j < E_; ++j) s2 += ebuf2[j];
        float noisy = logit + ebuf2[tid] / s2;
        noisy_s[tid] = noisy;
        if (out_size >= 2 * B_ * E_)
            out[B_ * E_ + b * E_ + tid] = noisy;   // second output: noisy
    }
    __syncthreads();

    if (tid < E_) {
        // stable descending rank (ties -> lower index first)
        const float myv = noisy_s[tid];
        int rank = 0;
#pragma unroll
        for (int j = 0; j < E_; ++j) {
            float vj = noisy_s[j];
            rank += (vj > myv) || (vj == myv && j < tid);
        }
        const int k = mis_mask[b];
        float sp = (rank < k) ? myv : 0.f;
        if (k < E_ && tid == 0) sp = 0.f;   // torch pad-scatter quirk
        sparse_s[tid] = sp;
    }
    __syncthreads();

    if (tid < E_) {
        float m3 = -INFINITY;
#pragma unroll
        for (int j = 0; j < E_; ++j) m3 = fmaxf(m3, sparse_s[j]);
        ebuf1[tid] = expf(sparse_s[tid] - m3);
    }
    __syncthreads();

    if (tid < E_) {
        float s3 = 0.f;
#pragma unroll
        for (int j = 0; j < E_; ++j) s3 += ebuf1[j];
        out[b * E_ + tid] = ebuf1[tid] / s3;       // first output: router_output
    }
}

extern "C" void kernel_launch(void* const* d_in, const int* in_sizes, int n_in,
                              void* d_out, int out_size) {
    const float* mh        = (const float*)d_in[0];
    const float* W_route   = (const float*)d_in[1];
    const float* b_route   = (const float*)d_in[2];
    const float* W_noise   = (const float*)d_in[3];
    const float* b_noise   = (const float*)d_in[4];
    const float* noise_eps = (const float*)d_in[5];
    const int*   mis_mask  = (const int*)d_in[6];
    float* out = (float*)d_out;

    fused_batch_kernel<<<B_, 1024>>>(mh, W_route, b_route, W_noise, b_noise,
                                     noise_eps, mis_mask, out, out_size);
}